// round 3
// baseline (speedup 1.0000x reference)
#include <cuda_runtime.h>
#include <cstdint>

// Problem constants (fixed by the dataset)
#define NN   50000
#define EI   400000          // raw edges
#define EEv  450000          // edges + self loops
#define HC   256             // H*C (layer-1 width) == IN
#define OUTD 16
#define NEG  0.2f
#define NB1  49              // ceil(NN/1024)

// ---------------- scratch (static device globals; no allocs) ----------------
__device__ float g_xl1[NN * HC];
__device__ float g_xr1[NN * HC];
__device__ float g_h  [NN * HC];
__device__ float g_xl2[NN * OUTD];
__device__ float g_xr2[NN * OUTD];
__device__ int   g_deg [NN];       // zero at start of every call (BSS init / re-zeroed by k_scatter)
__device__ int   g_ex  [NN];
__device__ int   g_off [NN + 1];
__device__ int   g_cur [NN];
__device__ int   g_csrc[EEv];
__device__ int   g_bsum[64];

// ---------------- CSR build ----------------
__global__ void k_hist(const int* __restrict__ ei) {
    int e = blockIdx.x * 256 + threadIdx.x;
    if (e >= EEv) return;
    int d = (e < EI) ? ei[EI + e] : (e - EI);
    atomicAdd(&g_deg[d], 1);
}

__global__ void k_scan1() {
    int i = blockIdx.x * 1024 + threadIdx.x;
    int v = (i < NN) ? g_deg[i] : 0;
    int x = v;
    #pragma unroll
    for (int o = 1; o < 32; o <<= 1) {
        int y = __shfl_up_sync(0xffffffffu, x, o);
        if ((threadIdx.x & 31) >= o) x += y;
    }
    __shared__ int ws[32];
    if ((threadIdx.x & 31) == 31) ws[threadIdx.x >> 5] = x;
    __syncthreads();
    if (threadIdx.x < 32) {
        int s = ws[threadIdx.x];
        #pragma unroll
        for (int o = 1; o < 32; o <<= 1) {
            int y = __shfl_up_sync(0xffffffffu, s, o);
            if (threadIdx.x >= (unsigned)o) s += y;
        }
        ws[threadIdx.x] = s;
    }
    __syncthreads();
    int incl = x + ((threadIdx.x >= 32) ? ws[(threadIdx.x >> 5) - 1] : 0);
    if (i < NN) g_ex[i] = incl - v;
    if (threadIdx.x == 1023) g_bsum[blockIdx.x] = incl;
}

// k_off with the 49-element block-sum scan inlined (replaces the old k_scan2)
__global__ void k_off() {
    __shared__ int s_pre[2];
    int t = threadIdx.x;
    int gb = blockIdx.x >> 2;   // which 1024-group this block belongs to
    if (t < 64) {
        int v = (t < gb && t < NB1) ? g_bsum[t] : 0;
        #pragma unroll
        for (int o = 16; o >= 1; o >>= 1) v += __shfl_xor_sync(0xffffffffu, v, o);
        if ((t & 31) == 0) s_pre[t >> 5] = v;
    }
    __syncthreads();
    int pre = s_pre[0] + s_pre[1];
    int i = blockIdx.x * 256 + t;
    if (i < NN) {
        int o = g_ex[i] + pre;
        g_off[i] = o;
        g_cur[i] = o;
    }
    if (i == 0) g_off[NN] = EEv;
}

__global__ void k_scatter(const int* __restrict__ ei) {
    int e = blockIdx.x * 256 + threadIdx.x;
    if (e < NN) g_deg[e] = 0;   // re-zero for the next call (scan1 already consumed it)
    if (e >= EEv) return;
    int s = (e < EI) ? ei[e]      : (e - EI);
    int d = (e < EI) ? ei[EI + e] : (e - EI);
    int p = atomicAdd(&g_cur[d], 1);
    g_csrc[p] = s;
}

// ---------------- tf32 mma helpers ----------------
__device__ __forceinline__ uint32_t f2tf(float f) {
    uint32_t u;
    asm("cvt.rna.tf32.f32 %0, %1;" : "=r"(u) : "f"(f));
    return u;
}

__device__ __forceinline__ void mma8(float* c, const uint32_t* a, const uint32_t* b) {
    asm volatile(
        "mma.sync.aligned.m16n8k8.row.col.f32.tf32.tf32.f32 "
        "{%0,%1,%2,%3},{%4,%5,%6,%7},{%8,%9},{%0,%1,%2,%3};\n"
        : "+f"(c[0]), "+f"(c[1]), "+f"(c[2]), "+f"(c[3])
        : "r"(a[0]), "r"(a[1]), "r"(a[2]), "r"(a[3]), "r"(b[0]), "r"(b[1]));
}

__device__ __forceinline__ void cp16(uint32_t dst, const void* src, int sz) {
    asm volatile("cp.async.cg.shared.global [%0], [%1], 16, %2;\n"
                 :: "r"(dst), "l"(src), "r"(sz));
}
__device__ __forceinline__ void cpcommit() { asm volatile("cp.async.commit_group;\n" ::: "memory"); }
__device__ __forceinline__ void cpwait0()  { asm volatile("cp.async.wait_group 0;\n" ::: "memory"); }

// ---------------- layer-1 fused GEMM: xl1 = X@Wl1+bl1  AND  xr1 = X@Wr1+br1
// BM=128, BN=128, BK=16; 512 threads (16 warps: 4m x 4n), warp tile 32x32 per output.
// A tile staged once, shared by both outputs. tf32 conversion done at STS time.
#define AP1 20    // 16 + 4 pad (conflict-free: (20*r + c) % 32 distinct for r<8,c<4)
#define BP1 136   // 128 + 8 pad (conflict-free: (136*k + n) % 32 distinct over 4k x 8n)
__global__ __launch_bounds__(512) void k_gemm1(
    const float* __restrict__ X,
    const float* __restrict__ W0, const float* __restrict__ b0,
    const float* __restrict__ W1, const float* __restrict__ b1)
{
    extern __shared__ float smem[];
    float* As  = smem;                     // [2][128*AP1]
    float* Bs0 = As  + 2 * 128 * AP1;      // [2][16*BP1]
    float* Bs1 = Bs0 + 2 * 16  * BP1;      // [2][16*BP1]

    int m0 = blockIdx.x * 128;
    int n0 = blockIdx.y * 128;
    int t = threadIdx.x;
    int warp = t >> 5, lane = t & 31;
    int wm = warp & 3, wn = warp >> 2;
    int ar = lane >> 2, ac = lane & 3;

    // accumulators: [out(l/r)][mt][nt][quad]
    float c0[2][4][4], c1[2][4][4];
    #pragma unroll
    for (int mt = 0; mt < 2; mt++)
        #pragma unroll
        for (int nt = 0; nt < 4; nt++)
            #pragma unroll
            for (int q = 0; q < 4; q++) { c0[mt][nt][q] = 0.f; c1[mt][nt][q] = 0.f; }

    // staging registers
    float4 va, vb0, vb1;
    int arow = t >> 2;               // 0..127
    int acol = (t & 3) * 4;          // 0,4,8,12
    int brow = t >> 5;               // 0..15
    int bcol = (t & 31) * 4;         // 0..124
    const float* aptr = X + (size_t)(m0 + arow) * 256 + acol;
    bool aok = (m0 + arow) < NN;

    auto ldg = [&](int kb) {
        va  = aok ? *(const float4*)(aptr + kb) : make_float4(0.f, 0.f, 0.f, 0.f);
        vb0 = *(const float4*)&W0[(size_t)(kb + brow) * 256 + n0 + bcol];
        vb1 = *(const float4*)&W1[(size_t)(kb + brow) * 256 + n0 + bcol];
    };
    auto sts = [&](int s) {
        float* ad  = As  + s * 128 * AP1 + arow * AP1 + acol;
        float* bd0 = Bs0 + s * 16  * BP1 + brow * BP1 + bcol;
        float* bd1 = Bs1 + s * 16  * BP1 + brow * BP1 + bcol;
        ad[0]  = __uint_as_float(f2tf(va.x));  ad[1]  = __uint_as_float(f2tf(va.y));
        ad[2]  = __uint_as_float(f2tf(va.z));  ad[3]  = __uint_as_float(f2tf(va.w));
        bd0[0] = __uint_as_float(f2tf(vb0.x)); bd0[1] = __uint_as_float(f2tf(vb0.y));
        bd0[2] = __uint_as_float(f2tf(vb0.z)); bd0[3] = __uint_as_float(f2tf(vb0.w));
        bd1[0] = __uint_as_float(f2tf(vb1.x)); bd1[1] = __uint_as_float(f2tf(vb1.y));
        bd1[2] = __uint_as_float(f2tf(vb1.z)); bd1[3] = __uint_as_float(f2tf(vb1.w));
    };

    ldg(0);

    #pragma unroll 1
    for (int i = 0; i < 16; i++) {
        int s = i & 1;
        sts(s);
        __syncthreads();
        if (i < 15) ldg((i + 1) * 16);

        const float* Ac  = As  + s * 128 * AP1;
        const float* Bc0 = Bs0 + s * 16  * BP1;
        const float* Bc1 = Bs1 + s * 16  * BP1;
        #pragma unroll
        for (int ks = 0; ks < 2; ks++) {
            int k = ks * 8;
            uint32_t a[2][4], bb0[4][2], bb1[4][2];
            #pragma unroll
            for (int mt = 0; mt < 2; mt++) {
                int m = wm * 32 + mt * 16;
                a[mt][0] = __float_as_uint(Ac[(m + ar)     * AP1 + k + ac]);
                a[mt][1] = __float_as_uint(Ac[(m + ar + 8) * AP1 + k + ac]);
                a[mt][2] = __float_as_uint(Ac[(m + ar)     * AP1 + k + ac + 4]);
                a[mt][3] = __float_as_uint(Ac[(m + ar + 8) * AP1 + k + ac + 4]);
            }
            #pragma unroll
            for (int nt = 0; nt < 4; nt++) {
                int n = wn * 32 + nt * 8 + ar;
                bb0[nt][0] = __float_as_uint(Bc0[(k + ac)     * BP1 + n]);
                bb0[nt][1] = __float_as_uint(Bc0[(k + ac + 4) * BP1 + n]);
                bb1[nt][0] = __float_as_uint(Bc1[(k + ac)     * BP1 + n]);
                bb1[nt][1] = __float_as_uint(Bc1[(k + ac + 4) * BP1 + n]);
            }
            #pragma unroll
            for (int mt = 0; mt < 2; mt++)
                #pragma unroll
                for (int nt = 0; nt < 4; nt++) {
                    mma8(c0[mt][nt], a[mt], bb0[nt]);
                    mma8(c1[mt][nt], a[mt], bb1[nt]);
                }
        }
        __syncthreads();
    }

    // epilogue: + bias, store both outputs
    #pragma unroll
    for (int mt = 0; mt < 2; mt++) {
        #pragma unroll
        for (int nt = 0; nt < 4; nt++) {
            int gr = m0 + wm * 32 + mt * 16 + ar;
            int gc = n0 + wn * 32 + nt * 8 + ac * 2;
            float l0 = b0[gc], l1 = b0[gc + 1];
            float r0 = b1[gc], r1 = b1[gc + 1];
            if (gr < NN) {
                float2 v;
                v.x = c0[mt][nt][0] + l0; v.y = c0[mt][nt][1] + l1;
                *(float2*)&g_xl1[(size_t)gr * HC + gc] = v;
                v.x = c1[mt][nt][0] + r0; v.y = c1[mt][nt][1] + r1;
                *(float2*)&g_xr1[(size_t)gr * HC + gc] = v;
            }
            if (gr + 8 < NN) {
                float2 v;
                v.x = c0[mt][nt][2] + l0; v.y = c0[mt][nt][3] + l1;
                *(float2*)&g_xl1[(size_t)(gr + 8) * HC + gc] = v;
                v.x = c1[mt][nt][2] + r0; v.y = c1[mt][nt][3] + r1;
                *(float2*)&g_xr1[(size_t)(gr + 8) * HC + gc] = v;
            }
        }
    }
}

// ---------------- layer-1 attention + online-softmax aggregation ----------------
__global__ __launch_bounds__(256) void k_agg1(const float* __restrict__ att,
                                              const float* __restrict__ b1)
{
    int gw   = (blockIdx.x * 256 + threadIdx.x) >> 5;
    int lane = threadIdx.x & 31;
    if (gw >= NN) return;
    int c0 = lane * 8;

    const float4* xrp = (const float4*)&g_xr1[(size_t)gw * HC + c0];
    float4 xr0 = xrp[0], xr1 = xrp[1];
    const float4* ap = (const float4*)&att[c0];
    float4 at0 = ap[0], at1 = ap[1];

    float acc[8];
    #pragma unroll
    for (int q = 0; q < 8; q++) acc[q] = 0.f;
    float den = 0.f, mx = -1e30f;

    int off = g_off[gw], dg = g_off[gw + 1] - off;
    for (int i = 0; i < dg; i++) {
        int s = g_csrc[off + i];
        const float4* vp = (const float4*)&g_xl1[(size_t)s * HC + c0];
        float4 v0 = vp[0], v1 = vp[1];
        float m, l, p;
        m = v0.x + xr0.x; l = (m > 0.f) ? m : NEG * m; p  = l * at0.x;
        m = v0.y + xr0.y; l = (m > 0.f) ? m : NEG * m; p += l * at0.y;
        m = v0.z + xr0.z; l = (m > 0.f) ? m : NEG * m; p += l * at0.z;
        m = v0.w + xr0.w; l = (m > 0.f) ? m : NEG * m; p += l * at0.w;
        m = v1.x + xr1.x; l = (m > 0.f) ? m : NEG * m; p += l * at1.x;
        m = v1.y + xr1.y; l = (m > 0.f) ? m : NEG * m; p += l * at1.y;
        m = v1.z + xr1.z; l = (m > 0.f) ? m : NEG * m; p += l * at1.z;
        m = v1.w + xr1.w; l = (m > 0.f) ? m : NEG * m; p += l * at1.w;
        p += __shfl_xor_sync(0xffffffffu, p, 1);
        p += __shfl_xor_sync(0xffffffffu, p, 2);
        p += __shfl_xor_sync(0xffffffffu, p, 4);
        float mn   = fmaxf(mx, p);
        float corr = __expf(mx - mn);
        float w    = __expf(p - mn);
        mx  = mn;
        den = den * corr + w;
        acc[0] = acc[0] * corr + w * v0.x;
        acc[1] = acc[1] * corr + w * v0.y;
        acc[2] = acc[2] * corr + w * v0.z;
        acc[3] = acc[3] * corr + w * v0.w;
        acc[4] = acc[4] * corr + w * v1.x;
        acc[5] = acc[5] * corr + w * v1.y;
        acc[6] = acc[6] * corr + w * v1.z;
        acc[7] = acc[7] * corr + w * v1.w;
    }
    float inv = 1.f / (den + 1e-16f);
    float4 o0, o1;
    o0.x = tanhf(acc[0] * inv + b1[c0 + 0]);
    o0.y = tanhf(acc[1] * inv + b1[c0 + 1]);
    o0.z = tanhf(acc[2] * inv + b1[c0 + 2]);
    o0.w = tanhf(acc[3] * inv + b1[c0 + 3]);
    o1.x = tanhf(acc[4] * inv + b1[c0 + 4]);
    o1.y = tanhf(acc[5] * inv + b1[c0 + 5]);
    o1.z = tanhf(acc[6] * inv + b1[c0 + 6]);
    o1.w = tanhf(acc[7] * inv + b1[c0 + 7]);
    float4* hp = (float4*)&g_h[(size_t)gw * HC + c0];
    hp[0] = o0; hp[1] = o1;
}

// ---------------- layer-2 GEMM (tf32 tensor cores): [xl2|xr2] = h @ [Wl2|Wr2] + b
// BM=128, BN=32, BK=32; B (256x32) fully SMEM-resident; A 2-stage cp.async
#define AP2 36
#define BP2 40
__global__ __launch_bounds__(256) void k_gemm2(
    const float* __restrict__ Wl2, const float* __restrict__ bl2,
    const float* __restrict__ Wr2, const float* __restrict__ br2)
{
    extern __shared__ float smem[];
    float* As = smem;                  // [2][128*AP2]
    float* Bs = smem + 2 * 128 * AP2;  // [256*BP2]
    float* bs = Bs + 256 * BP2;        // [32]

    int m0 = blockIdx.x * 128;
    int t = threadIdx.x;
    int warp = t >> 5, lane = t & 31;
    int ar = lane >> 2, ac = lane & 3;

    // load B (concat Wl2|Wr2) once
    #pragma unroll
    for (int i = 0; i < 8; i++) {
        int idx = t + i * 256;       // 0..2047
        int r   = idx >> 3;          // 0..255
        int c4  = (idx & 7) * 4;     // 0..28
        const float* src = (c4 < 16) ? (Wl2 + r * 16 + c4) : (Wr2 + r * 16 + c4 - 16);
        float4 v = *(const float4*)src;
        float* d = Bs + r * BP2 + c4;
        d[0] = v.x; d[1] = v.y; d[2] = v.z; d[3] = v.w;
    }
    if (t < 32) bs[t] = (t < 16) ? bl2[t] : br2[t - 16];

    uint32_t aS = (uint32_t)__cvta_generic_to_shared(As);

    float c[4][4];
    #pragma unroll
    for (int nt = 0; nt < 4; nt++)
        #pragma unroll
        for (int q = 0; q < 4; q++) c[nt][q] = 0.f;

    auto load_stage = [&](int s, int kb) {
        uint32_t ab = aS + (uint32_t)(s * 128 * AP2) * 4u;
        #pragma unroll
        for (int i = 0; i < 4; i++) {
            int r  = (t >> 3) + i * 32;
            int c4 = (t & 7) * 4;
            int gr = m0 + r;
            const float* src = g_h + (size_t)gr * 256 + kb + c4;
            cp16(ab + (uint32_t)(r * AP2 + c4) * 4u, src, (gr < NN) ? 16 : 0);
        }
    };

    load_stage(0, 0);
    cpcommit();

    for (int i = 0; i < 8; i++) {
        cpwait0();
        __syncthreads();
        if (i + 1 < 8) { load_stage((i + 1) & 1, (i + 1) * 32); cpcommit(); }

        const float* Ac = As + (i & 1) * 128 * AP2;
        int kb = i * 32;
        #pragma unroll
        for (int ks = 0; ks < 4; ks++) {
            int k = ks * 8;
            uint32_t a[4], b[4][2];
            int m = warp * 16;
            a[0] = f2tf(Ac[(m + ar)     * AP2 + k + ac]);
            a[1] = f2tf(Ac[(m + ar + 8) * AP2 + k + ac]);
            a[2] = f2tf(Ac[(m + ar)     * AP2 + k + ac + 4]);
            a[3] = f2tf(Ac[(m + ar + 8) * AP2 + k + ac + 4]);
            #pragma unroll
            for (int nt = 0; nt < 4; nt++) {
                int n = nt * 8 + ar;
                b[nt][0] = f2tf(Bs[(kb + k + ac)     * BP2 + n]);
                b[nt][1] = f2tf(Bs[(kb + k + ac + 4) * BP2 + n]);
            }
            #pragma unroll
            for (int nt = 0; nt < 4; nt++)
                mma8(c[nt], a, b[nt]);
        }
        __syncthreads();
    }

    // epilogue: + bias, split store into xl2 / xr2
    #pragma unroll
    for (int nt = 0; nt < 4; nt++) {
        int gr = m0 + warp * 16 + ar;
        int gc = nt * 8 + ac * 2;
        float bv0 = bs[gc], bv1 = bs[gc + 1];
        float* base = (gc < 16) ? g_xl2 : g_xr2;
        int col = (gc < 16) ? gc : gc - 16;
        if (gr < NN) {
            float2 v; v.x = c[nt][0] + bv0; v.y = c[nt][1] + bv1;
            *(float2*)&base[(size_t)gr * OUTD + col] = v;
        }
        if (gr + 8 < NN) {
            float2 v; v.x = c[nt][2] + bv0; v.y = c[nt][3] + bv1;
            *(float2*)&base[(size_t)(gr + 8) * OUTD + col] = v;
        }
    }
}

// ---------------- layer-2 aggregation + bias + log_softmax -> d_out ----------
__global__ __launch_bounds__(256) void k_agg2(const float* __restrict__ att2,
                                              const float* __restrict__ b2,
                                              float* __restrict__ out,
                                              int out_size)
{
    int gw   = (blockIdx.x * 256 + threadIdx.x) >> 5;
    int lane = threadIdx.x & 31;
    if (gw >= NN) return;
    int j = lane & 15;

    float xr = g_xr2[(size_t)gw * OUTD + j];
    float at = att2[j];
    float acc = 0.f, den = 0.f, mx = -1e30f;

    int off = g_off[gw], dg = g_off[gw + 1] - off;
    for (int i = 0; i < dg; i++) {
        int s = g_csrc[off + i];
        float v = g_xl2[(size_t)s * OUTD + j];
        float m = v + xr;
        float l = (m > 0.f) ? m : NEG * m;
        float p = l * at;
        p += __shfl_xor_sync(0xffffffffu, p, 1);
        p += __shfl_xor_sync(0xffffffffu, p, 2);
        p += __shfl_xor_sync(0xffffffffu, p, 4);
        p += __shfl_xor_sync(0xffffffffu, p, 8);
        float mn   = fmaxf(mx, p);
        float corr = __expf(mx - mn);
        float w    = __expf(p - mn);
        mx  = mn;
        den = den * corr + w;
        acc = acc * corr + w * v;
    }
    float o = acc / (den + 1e-16f) + b2[j];

    float mo = o;
    mo = fmaxf(mo, __shfl_xor_sync(0xffffffffu, mo, 1));
    mo = fmaxf(mo, __shfl_xor_sync(0xffffffffu, mo, 2));
    mo = fmaxf(mo, __shfl_xor_sync(0xffffffffu, mo, 4));
    mo = fmaxf(mo, __shfl_xor_sync(0xffffffffu, mo, 8));
    float ex = __expf(o - mo);
    float se = ex;
    se += __shfl_xor_sync(0xffffffffu, se, 1);
    se += __shfl_xor_sync(0xffffffffu, se, 2);
    se += __shfl_xor_sync(0xffffffffu, se, 4);
    se += __shfl_xor_sync(0xffffffffu, se, 8);
    float ls = o - mo - logf(se);

    if (lane < 16) {
        int i0 = gw * OUTD + j;
        if (i0 < out_size) out[i0] = o;
        int i1 = NN * OUTD + gw * OUTD + j;
        if (i1 < out_size) out[i1] = ls;
    }
}

// ---------------- launch ----------------
extern "C" void kernel_launch(void* const* d_in, const int* in_sizes, int n_in,
                              void* d_out, int out_size)
{
    const float* x     = (const float*)d_in[0];
    const int*   ei    = (const int*)  d_in[1];
    const float* Wl1   = (const float*)d_in[2];
    const float* bl1   = (const float*)d_in[3];
    const float* Wr1   = (const float*)d_in[4];
    const float* br1   = (const float*)d_in[5];
    const float* att1  = (const float*)d_in[6];
    const float* bias1 = (const float*)d_in[7];
    const float* Wl2   = (const float*)d_in[8];
    const float* bl2   = (const float*)d_in[9];
    const float* Wr2   = (const float*)d_in[10];
    const float* br2   = (const float*)d_in[11];
    const float* att2  = (const float*)d_in[12];
    const float* bias2 = (const float*)d_in[13];
    float* out = (float*)d_out;

    const int smem1 = (2 * 128 * AP1 + 4 * 16 * BP1) * 4;          // 55296 B
    const int smem2 = (2 * 128 * AP2 + 256 * BP2 + 32) * 4;        // 77952 B
    cudaFuncSetAttribute(k_gemm1, cudaFuncAttributeMaxDynamicSharedMemorySize, smem1);
    cudaFuncSetAttribute(k_gemm2, cudaFuncAttributeMaxDynamicSharedMemorySize, smem2);

    // launch order chosen so the big GEMM sits at index 3 (where ncu samples)
    k_hist   <<<(EEv + 255) / 256, 256>>>(ei);          // 0
    k_scan1  <<<NB1, 1024>>>();                         // 1
    k_off    <<<(NN + 255) / 256, 256>>>();             // 2
    dim3 g1((NN + 127) / 128, 2);
    k_gemm1  <<<g1, 512, smem1>>>(x, Wl1, bl1, Wr1, br1); // 3  <-- profiled
    k_scatter<<<(EEv + 255) / 256, 256>>>(ei);          // 4
    k_agg1   <<<(NN * 32 + 255) / 256, 256>>>(att1, bias1);           // 5
    k_gemm2  <<<(NN + 127) / 128, 256, smem2>>>(Wl2, bl2, Wr2, br2);  // 6
    k_agg2   <<<(NN * 32 + 255) / 256, 256>>>(att2, bias2, out, out_size); // 7
}

// round 4
// speedup vs baseline: 1.1270x; 1.1270x over previous
#include <cuda_runtime.h>
#include <cstdint>

// Problem constants (fixed by the dataset)
#define NN   50000
#define EI   400000          // raw edges
#define EEv  450000          // edges + self loops
#define HC   256             // H*C (layer-1 width) == IN
#define OUTD 16
#define NEG  0.2f
#define NB1  49              // ceil(NN/1024)

// ---------------- scratch (static device globals; no allocs) ----------------
__device__ float g_xl1[NN * HC];
__device__ float g_xr1[NN * HC];
__device__ float g_h  [NN * HC];
__device__ float g_xl2[NN * OUTD];
__device__ float g_xr2[NN * OUTD];
__device__ int   g_deg [NN];       // zero at start of every call (BSS init / re-zeroed by k_scatter)
__device__ int   g_ex  [NN];
__device__ int   g_off [NN + 1];
__device__ int   g_cur [NN];
__device__ int   g_csrc[EEv];
__device__ int   g_bsum[64];

// ---------------- CSR build ----------------
__global__ void k_hist(const int* __restrict__ ei) {
    int e = blockIdx.x * 256 + threadIdx.x;
    if (e >= EEv) return;
    int d = (e < EI) ? ei[EI + e] : (e - EI);
    atomicAdd(&g_deg[d], 1);
}

__global__ void k_scan1() {
    int i = blockIdx.x * 1024 + threadIdx.x;
    int v = (i < NN) ? g_deg[i] : 0;
    int x = v;
    #pragma unroll
    for (int o = 1; o < 32; o <<= 1) {
        int y = __shfl_up_sync(0xffffffffu, x, o);
        if ((threadIdx.x & 31) >= o) x += y;
    }
    __shared__ int ws[32];
    if ((threadIdx.x & 31) == 31) ws[threadIdx.x >> 5] = x;
    __syncthreads();
    if (threadIdx.x < 32) {
        int s = ws[threadIdx.x];
        #pragma unroll
        for (int o = 1; o < 32; o <<= 1) {
            int y = __shfl_up_sync(0xffffffffu, s, o);
            if (threadIdx.x >= (unsigned)o) s += y;
        }
        ws[threadIdx.x] = s;
    }
    __syncthreads();
    int incl = x + ((threadIdx.x >= 32) ? ws[(threadIdx.x >> 5) - 1] : 0);
    if (i < NN) g_ex[i] = incl - v;
    if (threadIdx.x == 1023) g_bsum[blockIdx.x] = incl;
}

// k_off with the 49-element block-sum scan inlined
__global__ void k_off() {
    __shared__ int s_pre[2];
    int t = threadIdx.x;
    int gb = blockIdx.x >> 2;   // which 1024-group this block belongs to
    if (t < 64) {
        int v = (t < gb && t < NB1) ? g_bsum[t] : 0;
        #pragma unroll
        for (int o = 16; o >= 1; o >>= 1) v += __shfl_xor_sync(0xffffffffu, v, o);
        if ((t & 31) == 0) s_pre[t >> 5] = v;
    }
    __syncthreads();
    int pre = s_pre[0] + s_pre[1];
    int i = blockIdx.x * 256 + t;
    if (i < NN) {
        int o = g_ex[i] + pre;
        g_off[i] = o;
        g_cur[i] = o;
    }
    if (i == 0) g_off[NN] = EEv;
}

__global__ void k_scatter(const int* __restrict__ ei) {
    int e = blockIdx.x * 256 + threadIdx.x;
    if (e < NN) g_deg[e] = 0;   // re-zero for the next call (scan1 already consumed it)
    if (e >= EEv) return;
    int s = (e < EI) ? ei[e]      : (e - EI);
    int d = (e < EI) ? ei[EI + e] : (e - EI);
    int p = atomicAdd(&g_cur[d], 1);
    g_csrc[p] = s;
}

// ---------------- tf32 mma helpers ----------------
__device__ __forceinline__ uint32_t f2tf(float f) {
    uint32_t u;
    asm("cvt.rna.tf32.f32 %0, %1;" : "=r"(u) : "f"(f));
    return u;
}

__device__ __forceinline__ void mma8(float* c, const uint32_t* a, const uint32_t* b) {
    asm volatile(
        "mma.sync.aligned.m16n8k8.row.col.f32.tf32.tf32.f32 "
        "{%0,%1,%2,%3},{%4,%5,%6,%7},{%8,%9},{%0,%1,%2,%3};\n"
        : "+f"(c[0]), "+f"(c[1]), "+f"(c[2]), "+f"(c[3])
        : "r"(a[0]), "r"(a[1]), "r"(a[2]), "r"(a[3]), "r"(b[0]), "r"(b[1]));
}

__device__ __forceinline__ void cp16(uint32_t dst, const void* src, int sz) {
    asm volatile("cp.async.cg.shared.global [%0], [%1], 16, %2;\n"
                 :: "r"(dst), "l"(src), "r"(sz));
}
__device__ __forceinline__ void cpcommit() { asm volatile("cp.async.commit_group;\n" ::: "memory"); }
__device__ __forceinline__ void cpwait0()  { asm volatile("cp.async.wait_group 0;\n" ::: "memory"); }
__device__ __forceinline__ void cpwait1()  { asm volatile("cp.async.wait_group 1;\n" ::: "memory"); }

// ---------------- layer-1 GEMM: xl1/xr1 = X @ W + b  (tf32, 3-stage cp.async)
// BM=128, BN=128, BK=32; 256 threads, 8 warps (4 m x 2 n), warp tile 32x64
// 3-stage ring, ONE __syncthreads per iteration.
#define AP1 36
#define BP1 136
__global__ __launch_bounds__(256, 2) void k_gemm1(
    const float* __restrict__ X,
    const float* __restrict__ W0, const float* __restrict__ b0,
    const float* __restrict__ W1, const float* __restrict__ b1)
{
    extern __shared__ float smem[];
    float* As = smem;                 // [3][128*AP1]
    float* Bs = smem + 3 * 128 * AP1; // [3][32*BP1]

    const float* W    = blockIdx.z ? W1 : W0;
    const float* bias = blockIdx.z ? b1 : b0;
    float*       Cg   = blockIdx.z ? g_xr1 : g_xl1;

    int m0 = blockIdx.x * 128;
    int n0 = blockIdx.y * 128;
    int t = threadIdx.x;
    int warp = t >> 5, lane = t & 31;
    int wm = warp & 3, wn = warp >> 2;
    int ar = lane >> 2, ac = lane & 3;

    uint32_t aS = (uint32_t)__cvta_generic_to_shared(As);
    uint32_t bS = (uint32_t)__cvta_generic_to_shared(Bs);

    float c[2][8][4];
    #pragma unroll
    for (int mt = 0; mt < 2; mt++)
        #pragma unroll
        for (int nt = 0; nt < 8; nt++)
            #pragma unroll
            for (int q = 0; q < 4; q++) c[mt][nt][q] = 0.f;

    auto load_stage = [&](int s, int kb) {
        uint32_t ab = aS + (uint32_t)(s * 128 * AP1) * 4u;
        uint32_t bb = bS + (uint32_t)(s * 32 * BP1) * 4u;
        #pragma unroll
        for (int i = 0; i < 4; i++) {
            int r  = (t >> 3) + i * 32;
            int c4 = (t & 7) * 4;
            int gr = m0 + r;
            const float* src = X + (size_t)gr * 256 + kb + c4;
            cp16(ab + (uint32_t)(r * AP1 + c4) * 4u, src, (gr < NN) ? 16 : 0);
        }
        #pragma unroll
        for (int i = 0; i < 4; i++) {
            int idx = t + i * 256;
            int r   = idx >> 5;
            int c4  = (idx & 31) * 4;
            cp16(bb + (uint32_t)(r * BP1 + c4) * 4u, W + (size_t)(kb + r) * 256 + n0 + c4, 16);
        }
    };

    load_stage(0, 0);  cpcommit();
    load_stage(1, 32); cpcommit();

    #pragma unroll 1
    for (int i = 0; i < 8; i++) {
        if (i == 7) cpwait0(); else cpwait1();
        __syncthreads();
        if (i + 2 < 8) {
            int s2 = (i + 2) % 3;
            load_stage(s2, (i + 2) * 32);
            cpcommit();
        }

        int s = i % 3;
        const float* Ac = As + s * 128 * AP1;
        const float* Bc = Bs + s * 32 * BP1;
        #pragma unroll
        for (int ks = 0; ks < 4; ks++) {
            int k = ks * 8;
            uint32_t a[2][4], b[8][2];
            #pragma unroll
            for (int mt = 0; mt < 2; mt++) {
                int m = wm * 32 + mt * 16;
                a[mt][0] = f2tf(Ac[(m + ar)     * AP1 + k + ac]);
                a[mt][1] = f2tf(Ac[(m + ar + 8) * AP1 + k + ac]);
                a[mt][2] = f2tf(Ac[(m + ar)     * AP1 + k + ac + 4]);
                a[mt][3] = f2tf(Ac[(m + ar + 8) * AP1 + k + ac + 4]);
            }
            #pragma unroll
            for (int nt = 0; nt < 8; nt++) {
                int n = wn * 64 + nt * 8 + ar;
                b[nt][0] = f2tf(Bc[(k + ac)     * BP1 + n]);
                b[nt][1] = f2tf(Bc[(k + ac + 4) * BP1 + n]);
            }
            #pragma unroll
            for (int mt = 0; mt < 2; mt++)
                #pragma unroll
                for (int nt = 0; nt < 8; nt++)
                    mma8(c[mt][nt], a[mt], b[nt]);
        }
    }

    // epilogue: + bias, store
    #pragma unroll
    for (int mt = 0; mt < 2; mt++) {
        #pragma unroll
        for (int nt = 0; nt < 8; nt++) {
            int gr = m0 + wm * 32 + mt * 16 + ar;
            int gc = n0 + wn * 64 + nt * 8 + ac * 2;
            float bv0 = bias[gc], bv1 = bias[gc + 1];
            if (gr < NN) {
                float2 v; v.x = c[mt][nt][0] + bv0; v.y = c[mt][nt][1] + bv1;
                *(float2*)&Cg[(size_t)gr * HC + gc] = v;
            }
            if (gr + 8 < NN) {
                float2 v; v.x = c[mt][nt][2] + bv0; v.y = c[mt][nt][3] + bv1;
                *(float2*)&Cg[(size_t)(gr + 8) * HC + gc] = v;
            }
        }
    }
}

// ---------------- layer-1 attention + online-softmax aggregation ----------------
__global__ __launch_bounds__(256) void k_agg1(const float* __restrict__ att,
                                              const float* __restrict__ b1)
{
    int gw   = (blockIdx.x * 256 + threadIdx.x) >> 5;
    int lane = threadIdx.x & 31;
    if (gw >= NN) return;
    int c0 = lane * 8;

    const float4* xrp = (const float4*)&g_xr1[(size_t)gw * HC + c0];
    float4 xr0 = xrp[0], xr1 = xrp[1];
    const float4* ap = (const float4*)&att[c0];
    float4 at0 = ap[0], at1 = ap[1];

    float acc[8];
    #pragma unroll
    for (int q = 0; q < 8; q++) acc[q] = 0.f;
    float den = 0.f, mx = -1e30f;

    int off = g_off[gw], dg = g_off[gw + 1] - off;
    for (int i = 0; i < dg; i++) {
        int s = g_csrc[off + i];
        const float4* vp = (const float4*)&g_xl1[(size_t)s * HC + c0];
        float4 v0 = vp[0], v1 = vp[1];
        float m, l, p;
        m = v0.x + xr0.x; l = (m > 0.f) ? m : NEG * m; p  = l * at0.x;
        m = v0.y + xr0.y; l = (m > 0.f) ? m : NEG * m; p += l * at0.y;
        m = v0.z + xr0.z; l = (m > 0.f) ? m : NEG * m; p += l * at0.z;
        m = v0.w + xr0.w; l = (m > 0.f) ? m : NEG * m; p += l * at0.w;
        m = v1.x + xr1.x; l = (m > 0.f) ? m : NEG * m; p += l * at1.x;
        m = v1.y + xr1.y; l = (m > 0.f) ? m : NEG * m; p += l * at1.y;
        m = v1.z + xr1.z; l = (m > 0.f) ? m : NEG * m; p += l * at1.z;
        m = v1.w + xr1.w; l = (m > 0.f) ? m : NEG * m; p += l * at1.w;
        p += __shfl_xor_sync(0xffffffffu, p, 1);
        p += __shfl_xor_sync(0xffffffffu, p, 2);
        p += __shfl_xor_sync(0xffffffffu, p, 4);
        float mn   = fmaxf(mx, p);
        float corr = __expf(mx - mn);
        float w    = __expf(p - mn);
        mx  = mn;
        den = den * corr + w;
        acc[0] = acc[0] * corr + w * v0.x;
        acc[1] = acc[1] * corr + w * v0.y;
        acc[2] = acc[2] * corr + w * v0.z;
        acc[3] = acc[3] * corr + w * v0.w;
        acc[4] = acc[4] * corr + w * v1.x;
        acc[5] = acc[5] * corr + w * v1.y;
        acc[6] = acc[6] * corr + w * v1.z;
        acc[7] = acc[7] * corr + w * v1.w;
    }
    float inv = 1.f / (den + 1e-16f);
    float4 o0, o1;
    o0.x = tanhf(acc[0] * inv + b1[c0 + 0]);
    o0.y = tanhf(acc[1] * inv + b1[c0 + 1]);
    o0.z = tanhf(acc[2] * inv + b1[c0 + 2]);
    o0.w = tanhf(acc[3] * inv + b1[c0 + 3]);
    o1.x = tanhf(acc[4] * inv + b1[c0 + 4]);
    o1.y = tanhf(acc[5] * inv + b1[c0 + 5]);
    o1.z = tanhf(acc[6] * inv + b1[c0 + 6]);
    o1.w = tanhf(acc[7] * inv + b1[c0 + 7]);
    float4* hp = (float4*)&g_h[(size_t)gw * HC + c0];
    hp[0] = o0; hp[1] = o1;
}

// ---------------- layer-2 GEMM (tf32 tensor cores): [xl2|xr2] = h @ [Wl2|Wr2] + b
// BM=128, BN=32, BK=32; B (256x32) fully SMEM-resident; A 2-stage cp.async
#define AP2 36
#define BP2 40
__global__ __launch_bounds__(256) void k_gemm2(
    const float* __restrict__ Wl2, const float* __restrict__ bl2,
    const float* __restrict__ Wr2, const float* __restrict__ br2)
{
    extern __shared__ float smem[];
    float* As = smem;                  // [2][128*AP2]
    float* Bs = smem + 2 * 128 * AP2;  // [256*BP2]
    float* bs = Bs + 256 * BP2;        // [32]

    int m0 = blockIdx.x * 128;
    int t = threadIdx.x;
    int warp = t >> 5, lane = t & 31;
    int ar = lane >> 2, ac = lane & 3;

    // load B (concat Wl2|Wr2) once
    #pragma unroll
    for (int i = 0; i < 8; i++) {
        int idx = t + i * 256;       // 0..2047
        int r   = idx >> 3;          // 0..255
        int c4  = (idx & 7) * 4;     // 0..28
        const float* src = (c4 < 16) ? (Wl2 + r * 16 + c4) : (Wr2 + r * 16 + c4 - 16);
        float4 v = *(const float4*)src;
        float* d = Bs + r * BP2 + c4;
        d[0] = v.x; d[1] = v.y; d[2] = v.z; d[3] = v.w;
    }
    if (t < 32) bs[t] = (t < 16) ? bl2[t] : br2[t - 16];

    uint32_t aS = (uint32_t)__cvta_generic_to_shared(As);

    float c[4][4];
    #pragma unroll
    for (int nt = 0; nt < 4; nt++)
        #pragma unroll
        for (int q = 0; q < 4; q++) c[nt][q] = 0.f;

    auto load_stage = [&](int s, int kb) {
        uint32_t ab = aS + (uint32_t)(s * 128 * AP2) * 4u;
        #pragma unroll
        for (int i = 0; i < 4; i++) {
            int r  = (t >> 3) + i * 32;
            int c4 = (t & 7) * 4;
            int gr = m0 + r;
            const float* src = g_h + (size_t)gr * 256 + kb + c4;
            cp16(ab + (uint32_t)(r * AP2 + c4) * 4u, src, (gr < NN) ? 16 : 0);
        }
    };

    load_stage(0, 0);
    cpcommit();

    for (int i = 0; i < 8; i++) {
        cpwait0();
        __syncthreads();
        if (i + 1 < 8) { load_stage((i + 1) & 1, (i + 1) * 32); cpcommit(); }

        const float* Ac = As + (i & 1) * 128 * AP2;
        int kb = i * 32;
        #pragma unroll
        for (int ks = 0; ks < 4; ks++) {
            int k = ks * 8;
            uint32_t a[4], b[4][2];
            int m = warp * 16;
            a[0] = f2tf(Ac[(m + ar)     * AP2 + k + ac]);
            a[1] = f2tf(Ac[(m + ar + 8) * AP2 + k + ac]);
            a[2] = f2tf(Ac[(m + ar)     * AP2 + k + ac + 4]);
            a[3] = f2tf(Ac[(m + ar + 8) * AP2 + k + ac + 4]);
            #pragma unroll
            for (int nt = 0; nt < 4; nt++) {
                int n = nt * 8 + ar;
                b[nt][0] = f2tf(Bs[(kb + k + ac)     * BP2 + n]);
                b[nt][1] = f2tf(Bs[(kb + k + ac + 4) * BP2 + n]);
            }
            #pragma unroll
            for (int nt = 0; nt < 4; nt++)
                mma8(c[nt], a, b[nt]);
        }
        __syncthreads();
    }

    // epilogue: + bias, split store into xl2 / xr2
    #pragma unroll
    for (int nt = 0; nt < 4; nt++) {
        int gr = m0 + warp * 16 + ar;
        int gc = nt * 8 + ac * 2;
        float bv0 = bs[gc], bv1 = bs[gc + 1];
        float* base = (gc < 16) ? g_xl2 : g_xr2;
        int col = (gc < 16) ? gc : gc - 16;
        if (gr < NN) {
            float2 v; v.x = c[nt][0] + bv0; v.y = c[nt][1] + bv1;
            *(float2*)&base[(size_t)gr * OUTD + col] = v;
        }
        if (gr + 8 < NN) {
            float2 v; v.x = c[nt][2] + bv0; v.y = c[nt][3] + bv1;
            *(float2*)&base[(size_t)(gr + 8) * OUTD + col] = v;
        }
    }
}

// ---------------- layer-2 aggregation + bias + log_softmax -> d_out ----------
__global__ __launch_bounds__(256) void k_agg2(const float* __restrict__ att2,
                                              const float* __restrict__ b2,
                                              float* __restrict__ out,
                                              int out_size)
{
    int gw   = (blockIdx.x * 256 + threadIdx.x) >> 5;
    int lane = threadIdx.x & 31;
    if (gw >= NN) return;
    int j = lane & 15;

    float xr = g_xr2[(size_t)gw * OUTD + j];
    float at = att2[j];
    float acc = 0.f, den = 0.f, mx = -1e30f;

    int off = g_off[gw], dg = g_off[gw + 1] - off;
    for (int i = 0; i < dg; i++) {
        int s = g_csrc[off + i];
        float v = g_xl2[(size_t)s * OUTD + j];
        float m = v + xr;
        float l = (m > 0.f) ? m : NEG * m;
        float p = l * at;
        p += __shfl_xor_sync(0xffffffffu, p, 1);
        p += __shfl_xor_sync(0xffffffffu, p, 2);
        p += __shfl_xor_sync(0xffffffffu, p, 4);
        p += __shfl_xor_sync(0xffffffffu, p, 8);
        float mn   = fmaxf(mx, p);
        float corr = __expf(mx - mn);
        float w    = __expf(p - mn);
        mx  = mn;
        den = den * corr + w;
        acc = acc * corr + w * v;
    }
    float o = acc / (den + 1e-16f) + b2[j];

    float mo = o;
    mo = fmaxf(mo, __shfl_xor_sync(0xffffffffu, mo, 1));
    mo = fmaxf(mo, __shfl_xor_sync(0xffffffffu, mo, 2));
    mo = fmaxf(mo, __shfl_xor_sync(0xffffffffu, mo, 4));
    mo = fmaxf(mo, __shfl_xor_sync(0xffffffffu, mo, 8));
    float ex = __expf(o - mo);
    float se = ex;
    se += __shfl_xor_sync(0xffffffffu, se, 1);
    se += __shfl_xor_sync(0xffffffffu, se, 2);
    se += __shfl_xor_sync(0xffffffffu, se, 4);
    se += __shfl_xor_sync(0xffffffffu, se, 8);
    float ls = o - mo - logf(se);

    if (lane < 16) {
        int i0 = gw * OUTD + j;
        if (i0 < out_size) out[i0] = o;
        int i1 = NN * OUTD + gw * OUTD + j;
        if (i1 < out_size) out[i1] = ls;
    }
}

// ---------------- launch ----------------
extern "C" void kernel_launch(void* const* d_in, const int* in_sizes, int n_in,
                              void* d_out, int out_size)
{
    const float* x     = (const float*)d_in[0];
    const int*   ei    = (const int*)  d_in[1];
    const float* Wl1   = (const float*)d_in[2];
    const float* bl1   = (const float*)d_in[3];
    const float* Wr1   = (const float*)d_in[4];
    const float* br1   = (const float*)d_in[5];
    const float* att1  = (const float*)d_in[6];
    const float* bias1 = (const float*)d_in[7];
    const float* Wl2   = (const float*)d_in[8];
    const float* bl2   = (const float*)d_in[9];
    const float* Wr2   = (const float*)d_in[10];
    const float* br2   = (const float*)d_in[11];
    const float* att2  = (const float*)d_in[12];
    const float* bias2 = (const float*)d_in[13];
    float* out = (float*)d_out;

    const int smem1 = 3 * (128 * AP1 + 32 * BP1) * 4;              // 107520 B
    const int smem2 = (2 * 128 * AP2 + 256 * BP2 + 32) * 4;        // 77952 B
    cudaFuncSetAttribute(k_gemm1, cudaFuncAttributeMaxDynamicSharedMemorySize, smem1);
    cudaFuncSetAttribute(k_gemm2, cudaFuncAttributeMaxDynamicSharedMemorySize, smem2);

    // launch order chosen so the big GEMM sits at index 3 (where ncu samples)
    k_hist   <<<(EEv + 255) / 256, 256>>>(ei);          // 0
    k_scan1  <<<NB1, 1024>>>();                         // 1
    k_off    <<<(NN + 255) / 256, 256>>>();             // 2
    dim3 g1((NN + 127) / 128, 2, 2);
    k_gemm1  <<<g1, 256, smem1>>>(x, Wl1, bl1, Wr1, br1); // 3  <-- profiled
    k_scatter<<<(EEv + 255) / 256, 256>>>(ei);          // 4
    k_agg1   <<<(NN * 32 + 255) / 256, 256>>>(att1, bias1);           // 5
    k_gemm2  <<<(NN + 127) / 128, 256, smem2>>>(Wl2, bl2, Wr2, br2);  // 6
    k_agg2   <<<(NN * 32 + 255) / 256, 256>>>(att2, bias2, out, out_size); // 7
}